// round 6
// baseline (speedup 1.0000x reference)
#include <cuda_runtime.h>
#include <cstdint>

// ---------------------------------------------------------------------------
// Problem constants (fixed by the dataset)
// ---------------------------------------------------------------------------
#define T_STEPS   1000
#define T_PAD     1008          // multiple of 16 for mma tiles
#define N_IN      700
#define K_PAD     704           // multiple of 32 for mma k
#define N_HID     4096
#define N_OUT     20

// ---------------------------------------------------------------------------
// Static device scratch (no runtime allocation)
// ---------------------------------------------------------------------------
__device__ int    g_esize;                         // 8 | 4 | -4(f32) | -8(f64)
__device__ int8_t g_spk [T_PAD * K_PAD];           // spikes int8, zero padded
__device__ int8_t g_w1s [N_HID * K_PAD];           // w1 int8, zero padded
__device__ int8_t g_v1T [(size_t)N_HID * N_HID];   // v1T[k][h] = v1[h][k]
__device__ int8_t g_w2s [N_OUT * N_HID];           // w2 int8
__device__ int    g_in  [T_PAD * N_HID];           // feed-forward currents

// ---------------------------------------------------------------------------
// Dtype-agnostic element load (values all fit int; conversions exact)
// ---------------------------------------------------------------------------
__device__ __forceinline__ int load_elem(const void* p, int es, size_t i) {
    if (es == 8)  return (int)((const long long*)p)[i];
    if (es == 4)  return ((const int*)p)[i];
    if (es == -4) return (int)((const float*)p)[i];
    return (int)((const double*)p)[i];
}

// ---------------------------------------------------------------------------
// Dtype sniffing on w2's raw words (values uniform in [-8,8), 81920 elems):
//  int64 : odd 32-bit words all in {0, 0xFFFFFFFF}
//  int32 : some odd word is a sign-extended small int other than 0/-1
//  f32   : nonzero words have exponent field ~0x7F..0x82
//  f64   : high (odd) words look float-like, low (even) words all zero
// Deterministic pure function of the input buffer.
// ---------------------------------------------------------------------------
__global__ void k_detect(const void* __restrict__ w2) {
    const unsigned* u = (const unsigned*)w2;
    int is_float = 0, odd_ok = 1, even_nz = 0;
    for (int i = 0; i < 2048; ++i) {
        unsigned w = u[i];
        unsigned e = (w >> 23) & 0xFFu;
        if (w != 0u && e >= 0x70u && e <= 0x90u) is_float = 1;
        if (i & 1) { if (w != 0u && w != 0xFFFFFFFFu) odd_ok = 0; }
        else       { if (w != 0u) even_nz = 1; }
    }
    g_esize = is_float ? (even_nz ? -4 : -8) : (odd_ok ? 8 : 4);
}

// ---------------------------------------------------------------------------
// Pack kernels (all branch on g_esize; stream order guarantees visibility)
// ---------------------------------------------------------------------------
__global__ void k_pack_spk(const void* __restrict__ spk) {
    int es = g_esize;
    int idx = blockIdx.x * blockDim.x + threadIdx.x;
    if (idx >= T_PAD * K_PAD) return;
    int t = idx / K_PAD, i = idx % K_PAD;
    int8_t v = 0;
    if (t < T_STEPS && i < N_IN) v = (int8_t)load_elem(spk, es, (size_t)t * N_IN + i);
    g_spk[idx] = v;
}

__global__ void k_pack_w1(const void* __restrict__ w1) {
    int es = g_esize;
    int idx = blockIdx.x * blockDim.x + threadIdx.x;
    if (idx >= N_HID * K_PAD) return;
    int h = idx / K_PAD, i = idx % K_PAD;
    int8_t v = 0;
    if (i < N_IN) v = (int8_t)load_elem(w1, es, (size_t)h * N_IN + i);
    g_w1s[idx] = v;
}

__global__ void k_pack_w2(const void* __restrict__ w2) {
    int es = g_esize;
    int idx = blockIdx.x * blockDim.x + threadIdx.x;
    if (idx >= N_OUT * N_HID) return;
    g_w2s[idx] = (int8_t)load_elem(w2, es, (size_t)idx);
}

// Tiled transpose v1[h][k] -> v1T[k][h] (int8)
__global__ void k_v1_transpose(const void* __restrict__ v1) {
    __shared__ int8_t tile[32][33];
    int es = g_esize;
    int bk = blockIdx.x * 32;   // k tile base
    int bh = blockIdx.y * 32;   // h tile base
    int x = threadIdx.x, y = threadIdx.y;
    tile[y][x] = (int8_t)load_elem(v1, es, (size_t)(bh + y) * N_HID + (bk + x));
    __syncthreads();
    g_v1T[(size_t)(bk + y) * N_HID + (bh + x)] = tile[x][y];
}

// ---------------------------------------------------------------------------
// in_all GEMM: g_in[t][h] = sum_i g_spk[t][i] * g_w1s[h][i]
// mma.sync.m16n8k32.s8 — one 16x8 tile per warp.
// ---------------------------------------------------------------------------
__global__ __launch_bounds__(256) void k_gemm_in() {
    int warp = (blockIdx.x * blockDim.x + threadIdx.x) >> 5;
    int lane = threadIdx.x & 31;
    int tt = warp / (N_HID / 8);
    int hh = warp % (N_HID / 8);
    int T0 = tt * 16;
    int H0 = hh * 8;

    int grp = lane >> 2;
    int tig = lane & 3;

    int d0 = 0, d1 = 0, d2 = 0, d3 = 0;

    const int8_t* arow0 = g_spk + (size_t)(T0 + grp)     * K_PAD;
    const int8_t* arow1 = g_spk + (size_t)(T0 + grp + 8) * K_PAD;
    const int8_t* brow  = g_w1s + (size_t)(H0 + grp)     * K_PAD;

    #pragma unroll 4
    for (int k0 = 0; k0 < K_PAD; k0 += 32) {
        int a0 = *(const int*)(arow0 + k0 + tig * 4);
        int a1 = *(const int*)(arow1 + k0 + tig * 4);
        int a2 = *(const int*)(arow0 + k0 + 16 + tig * 4);
        int a3 = *(const int*)(arow1 + k0 + 16 + tig * 4);
        int b0 = *(const int*)(brow  + k0 + tig * 4);
        int b1 = *(const int*)(brow  + k0 + 16 + tig * 4);
        asm volatile(
            "mma.sync.aligned.m16n8k32.row.col.s32.s8.s8.s32 "
            "{%0,%1,%2,%3}, {%4,%5,%6,%7}, {%8,%9}, {%0,%1,%2,%3};"
            : "+r"(d0), "+r"(d1), "+r"(d2), "+r"(d3)
            : "r"(a0), "r"(a1), "r"(a2), "r"(a3), "r"(b0), "r"(b1));
    }

    int* out0 = g_in + (size_t)(T0 + grp)     * N_HID + H0 + tig * 2;
    int* out1 = g_in + (size_t)(T0 + grp + 8) * N_HID + H0 + tig * 2;
    out0[0] = d0;  out0[1] = d1;
    out1[0] = d2;  out1[1] = d3;
}

// ---------------------------------------------------------------------------
// Persistent single-CTA recurrent kernel.
// 1024 threads; thread tid owns hidden neurons h = 4*tid + {0..3}.
// State lives in registers; spike lists double-buffered in SMEM; w2 in SMEM.
// ---------------------------------------------------------------------------
#define SM_W2_BYTES   (N_OUT * N_HID)                 // 81920
#define SM_LIST_OFF   SM_W2_BYTES
#define SM_CNT_OFF    (SM_W2_BYTES + 2 * N_HID * 2)
#define SM_TOTAL      (SM_CNT_OFF + 16)

__global__ __launch_bounds__(1024, 1) void k_persist(float* __restrict__ out)
{
    extern __shared__ char sm[];
    int8_t*         w2sh  = (int8_t*)sm;
    unsigned short* list0 = (unsigned short*)(sm + SM_LIST_OFF);
    unsigned short* list1 = list0 + N_HID;
    int*            cnt   = (int*)(sm + SM_CNT_OFF);

    const int tid = threadIdx.x;

    // copy w2 (already int8) into SMEM with 4B transfers
    for (int i = tid; i < (N_OUT * N_HID) / 4; i += 1024)
        ((int*)w2sh)[i] = ((const int*)g_w2s)[i];
    if (tid == 0) { cnt[0] = 0; cnt[1] = 0; }
    __syncthreads();

    int mem0 = 0, mem1 = 0, mem2 = 0, mem3 = 0;
    int syn0 = 0, syn1 = 0, syn2 = 0, syn3 = 0;
    unsigned prev = 0;
    int rmem = 0, rsyn = 0;

    const int hbase = tid * 4;

    for (int t = 0; t < T_STEPS; ++t) {
        const int p = t & 1;
        unsigned short* rd = p ? list0 : list1;   // written at t-1
        unsigned short* wr = p ? list1 : list0;   // written this step

        // feed-forward currents for this step
        const int4 inv = *(const int4*)(g_in + (size_t)t * N_HID + hbase);

        // sparse recurrent feedback from spikes(t-1), 4-way unrolled for MLP
        int n = cnt[p ^ 1];
        int fb0 = 0, fb1 = 0, fb2 = 0, fb3 = 0;
        int idx = 0;
        for (; idx + 4 <= n; idx += 4) {
            int k0 = rd[idx], k1 = rd[idx + 1], k2 = rd[idx + 2], k3 = rd[idx + 3];
            int wa = *(const int*)(g_v1T + (size_t)k0 * N_HID + hbase);
            int wb = *(const int*)(g_v1T + (size_t)k1 * N_HID + hbase);
            int wc = *(const int*)(g_v1T + (size_t)k2 * N_HID + hbase);
            int wd = *(const int*)(g_v1T + (size_t)k3 * N_HID + hbase);
            fb0 += ((wa << 24) >> 24) + ((wb << 24) >> 24) + ((wc << 24) >> 24) + ((wd << 24) >> 24);
            fb1 += ((wa << 16) >> 24) + ((wb << 16) >> 24) + ((wc << 16) >> 24) + ((wd << 16) >> 24);
            fb2 += ((wa <<  8) >> 24) + ((wb <<  8) >> 24) + ((wc <<  8) >> 24) + ((wd <<  8) >> 24);
            fb3 += (wa >> 24) + (wb >> 24) + (wc >> 24) + (wd >> 24);
        }
        for (; idx < n; ++idx) {
            int k = rd[idx];
            int w = *(const int*)(g_v1T + (size_t)k * N_HID + hbase);
            fb0 += (w << 24) >> 24;
            fb1 += (w << 16) >> 24;
            fb2 += (w <<  8) >> 24;
            fb3 += w >> 24;
        }

        __syncthreads();                       // A: reads of buffer (t-1) done
        if (tid == 0) cnt[p ^ 1] = 0;          // recycle for step t+1

        // hidden LIF: reset -> threshold -> decay/integrate
        unsigned newprev = 0;
        {
            int m, o;
            m = (prev & 1u) ? 0 : mem0;  o = (m > 1);
            mem0 = m - (m >> 3) + syn0;
            syn0 = syn0 - (syn0 >> 4) + inv.x + fb0;
            if (o) { int pos = atomicAdd(&cnt[p], 1); wr[pos] = (unsigned short)(hbase + 0); newprev |= 1u; }

            m = (prev & 2u) ? 0 : mem1;  o = (m > 1);
            mem1 = m - (m >> 3) + syn1;
            syn1 = syn1 - (syn1 >> 4) + inv.y + fb1;
            if (o) { int pos = atomicAdd(&cnt[p], 1); wr[pos] = (unsigned short)(hbase + 1); newprev |= 2u; }

            m = (prev & 4u) ? 0 : mem2;  o = (m > 1);
            mem2 = m - (m >> 3) + syn2;
            syn2 = syn2 - (syn2 >> 4) + inv.z + fb2;
            if (o) { int pos = atomicAdd(&cnt[p], 1); wr[pos] = (unsigned short)(hbase + 2); newprev |= 4u; }

            m = (prev & 8u) ? 0 : mem3;  o = (m > 1);
            mem3 = m - (m >> 3) + syn3;
            syn3 = syn3 - (syn3 >> 4) + inv.w + fb3;
            if (o) { int pos = atomicAdd(&cnt[p], 1); wr[pos] = (unsigned short)(hbase + 3); newprev |= 8u; }
        }
        prev = newprev;

        __syncthreads();                       // B: buffer (t) complete

        // readout LIF on 20 threads (uses THIS step's new spikes)
        if (tid < N_OUT) {
            int n2 = cnt[p];
            const int8_t* w2row = w2sh + tid * N_HID;
            int ro = 0;
            for (int i = 0; i < n2; ++i) ro += w2row[wr[i]];
            rmem = rmem - (rmem >> 3) + rsyn;        // old rsyn
            rsyn = rsyn - (rsyn >> 4) + ro;
            // Output buffer is float32 (rel-err comparison dtype); |rmem| < 2^24
            // so the conversion is exact.
            out[(size_t)tid * T_STEPS + t] = (float)rmem;
        }
    }
}

// ---------------------------------------------------------------------------
// Launch
// ---------------------------------------------------------------------------
extern "C" void kernel_launch(void* const* d_in, const int* in_sizes, int n_in,
                              void* d_out, int out_size) {
    // Robust input identification: all element counts are distinct.
    const void* spk = d_in[0];
    const void* w1  = d_in[1];
    const void* v1  = d_in[2];
    const void* w2  = d_in[3];
    for (int i = 0; i < n_in && i < 4; ++i) {
        int s = in_sizes[i];
        if      (s == T_STEPS * N_IN)  spk = d_in[i];
        else if (s == N_HID * N_IN)    w1  = d_in[i];
        else if (s == N_HID * N_HID)   v1  = d_in[i];
        else if (s == N_OUT * N_HID)   w2  = d_in[i];
    }

    k_detect<<<1, 1>>>(w2);

    k_pack_spk<<<(T_PAD * K_PAD + 255) / 256, 256>>>(spk);
    k_pack_w1 <<<(N_HID * K_PAD + 255) / 256, 256>>>(w1);
    k_pack_w2 <<<(N_OUT * N_HID + 255) / 256, 256>>>(w2);
    k_v1_transpose<<<dim3(N_HID / 32, N_HID / 32), dim3(32, 32)>>>(v1);

    k_gemm_in<<<(T_PAD / 16) * (N_HID / 8) / 8, 256>>>();

    cudaFuncSetAttribute(k_persist, cudaFuncAttributeMaxDynamicSharedMemorySize,
                         SM_TOTAL);
    k_persist<<<1, 1024, SM_TOTAL>>>((float*)d_out);
}

// round 7
// speedup vs baseline: 1.0777x; 1.0777x over previous
#include <cuda_runtime.h>
#include <cstdint>

// ---------------------------------------------------------------------------
// Problem constants (fixed by the dataset)
// ---------------------------------------------------------------------------
#define T_STEPS   1000
#define T_PAD     1008          // multiple of 16 for mma tiles
#define N_IN      700
#define K_PAD     704           // multiple of 32 for mma k
#define N_HID     4096
#define N_OUT     20

// ---------------------------------------------------------------------------
// Static device scratch (no runtime allocation)
// ---------------------------------------------------------------------------
__device__ int    g_esize;                         // 8 | 4 | -4(f32) | -8(f64)
__device__ int8_t g_spk [T_PAD * K_PAD];           // spikes int8, zero padded
__device__ int8_t g_w1s [N_HID * K_PAD];           // w1 int8, zero padded
__device__ int8_t g_v1T [(size_t)N_HID * N_HID];   // v1T[k][h] = v1[h][k]
__device__ int8_t g_w2s [N_OUT * N_HID];           // w2 int8
__device__ int    g_in  [T_PAD * N_HID];           // feed-forward currents

// ---------------------------------------------------------------------------
// Dtype-agnostic element load (values all fit int; conversions exact)
// ---------------------------------------------------------------------------
__device__ __forceinline__ int load_elem(const void* p, int es, size_t i) {
    if (es == 8)  return (int)((const long long*)p)[i];
    if (es == 4)  return ((const int*)p)[i];
    if (es == -4) return (int)((const float*)p)[i];
    return (int)((const double*)p)[i];
}

// ---------------------------------------------------------------------------
// Dtype sniffing on w2's raw words (values uniform in [-8,8)).
// Deterministic pure function of the input buffer.
// ---------------------------------------------------------------------------
__global__ void k_detect(const void* __restrict__ w2) {
    const unsigned* u = (const unsigned*)w2;
    int is_float = 0, odd_ok = 1, even_nz = 0;
    for (int i = 0; i < 512; ++i) {
        unsigned w = u[i];
        unsigned e = (w >> 23) & 0xFFu;
        if (w != 0u && e >= 0x70u && e <= 0x90u) is_float = 1;
        if (i & 1) { if (w != 0u && w != 0xFFFFFFFFu) odd_ok = 0; }
        else       { if (w != 0u) even_nz = 1; }
    }
    g_esize = is_float ? (even_nz ? -4 : -8) : (odd_ok ? 8 : 4);
}

// ---------------------------------------------------------------------------
// Pack kernels (all branch on g_esize; stream order guarantees visibility)
// ---------------------------------------------------------------------------
__global__ void k_pack_spk(const void* __restrict__ spk) {
    int es = g_esize;
    int idx = blockIdx.x * blockDim.x + threadIdx.x;
    if (idx >= T_PAD * K_PAD) return;
    int t = idx / K_PAD, i = idx % K_PAD;
    int8_t v = 0;
    if (t < T_STEPS && i < N_IN) v = (int8_t)load_elem(spk, es, (size_t)t * N_IN + i);
    g_spk[idx] = v;
}

__global__ void k_pack_w1(const void* __restrict__ w1) {
    int es = g_esize;
    int idx = blockIdx.x * blockDim.x + threadIdx.x;
    if (idx >= N_HID * K_PAD) return;
    int h = idx / K_PAD, i = idx % K_PAD;
    int8_t v = 0;
    if (i < N_IN) v = (int8_t)load_elem(w1, es, (size_t)h * N_IN + i);
    g_w1s[idx] = v;
}

__global__ void k_pack_w2(const void* __restrict__ w2) {
    int es = g_esize;
    int idx = blockIdx.x * blockDim.x + threadIdx.x;
    if (idx >= N_OUT * N_HID) return;
    g_w2s[idx] = (int8_t)load_elem(w2, es, (size_t)idx);
}

// Tiled transpose v1[h][k] -> v1T[k][h] (int8)
__global__ void k_v1_transpose(const void* __restrict__ v1) {
    __shared__ int8_t tile[32][33];
    int es = g_esize;
    int bk = blockIdx.x * 32;   // k tile base
    int bh = blockIdx.y * 32;   // h tile base
    int x = threadIdx.x, y = threadIdx.y;
    tile[y][x] = (int8_t)load_elem(v1, es, (size_t)(bh + y) * N_HID + (bk + x));
    __syncthreads();
    g_v1T[(size_t)(bk + y) * N_HID + (bh + x)] = tile[x][y];
}

// ---------------------------------------------------------------------------
// in_all GEMM: g_in[t][h] = sum_i g_spk[t][i] * g_w1s[h][i]
// Each warp computes a 16(T) x 64(H) tile: A fragment reused across 8 N-tiles.
// L2 traffic: 226 MB (vs 545 MB for 16x8 tiles).
// ---------------------------------------------------------------------------
__global__ __launch_bounds__(256) void k_gemm_in() {
    int warp = (blockIdx.x * blockDim.x + threadIdx.x) >> 5;   // 0..4031
    int lane = threadIdx.x & 31;
    int tt = warp / (N_HID / 64);        // 0..62
    int hh = warp % (N_HID / 64);        // 0..63
    int T0 = tt * 16;
    int H0 = hh * 64;

    int grp = lane >> 2;                 // 0..7
    int tig = lane & 3;                  // 0..3

    int acc[8][4];
    #pragma unroll
    for (int nt = 0; nt < 8; ++nt)
        acc[nt][0] = acc[nt][1] = acc[nt][2] = acc[nt][3] = 0;

    const int8_t* arow0 = g_spk + (size_t)(T0 + grp)     * K_PAD;
    const int8_t* arow1 = g_spk + (size_t)(T0 + grp + 8) * K_PAD;

    for (int k0 = 0; k0 < K_PAD; k0 += 32) {
        int a0 = *(const int*)(arow0 + k0 + tig * 4);
        int a1 = *(const int*)(arow1 + k0 + tig * 4);
        int a2 = *(const int*)(arow0 + k0 + 16 + tig * 4);
        int a3 = *(const int*)(arow1 + k0 + 16 + tig * 4);
        #pragma unroll
        for (int nt = 0; nt < 8; ++nt) {
            const int8_t* brow = g_w1s + (size_t)(H0 + nt * 8 + grp) * K_PAD;
            int b0 = *(const int*)(brow + k0 + tig * 4);
            int b1 = *(const int*)(brow + k0 + 16 + tig * 4);
            asm volatile(
                "mma.sync.aligned.m16n8k32.row.col.s32.s8.s8.s32 "
                "{%0,%1,%2,%3}, {%4,%5,%6,%7}, {%8,%9}, {%0,%1,%2,%3};"
                : "+r"(acc[nt][0]), "+r"(acc[nt][1]), "+r"(acc[nt][2]), "+r"(acc[nt][3])
                : "r"(a0), "r"(a1), "r"(a2), "r"(a3), "r"(b0), "r"(b1));
        }
    }

    #pragma unroll
    for (int nt = 0; nt < 8; ++nt) {
        int* out0 = g_in + (size_t)(T0 + grp)     * N_HID + H0 + nt * 8 + tig * 2;
        int* out1 = g_in + (size_t)(T0 + grp + 8) * N_HID + H0 + nt * 8 + tig * 2;
        out0[0] = acc[nt][0];  out0[1] = acc[nt][1];
        out1[0] = acc[nt][2];  out1[1] = acc[nt][3];
    }
}

// ---------------------------------------------------------------------------
// Persistent single-CTA recurrent kernel — ONE barrier per step.
// 1024 threads; thread tid owns hidden neurons h = 4*tid + {0..3}.
//
// Synchronization audit (single __syncthreads per step, BAR(t) after LIF):
//   lists (double-buffered):  LIF(t) writes L[t&1]; gather(t+1)/readout(t)
//     read it -> separated by BAR(t).  gather(t) reads L[(t+1)&1]; LIF(t+1)
//     overwrites it -> separated by BAR(t).  (RAW + WAR both covered.)
//   counters (triple-buffered, rotate read<-write<-zero):  gather(t) reads
//     cnt[ir]; LIF(t) atomics cnt[iw]; tid0 zeroes cnt[iz] (pre-barrier).
//     cnt[iz] was last read by gather(t-1) (before BAR(t-1)) and is next
//     written by LIF(t+1) atomics (after BAR(t)) -> no conflict, no extra
//     barrier needed.
//   readout(t) (tid<20, post-barrier) reads L[t&1]/cnt[iw(t)] concurrently
//     with other threads' gather(t+1) (same data, read-read) and LIF(t+1)
//     (different buffers). Safe.
// ---------------------------------------------------------------------------
#define SM_W2_BYTES   (N_OUT * N_HID)                 // 81920
#define SM_LIST_OFF   SM_W2_BYTES
#define SM_CNT_OFF    (SM_W2_BYTES + 2 * N_HID * 2)
#define SM_TOTAL      (SM_CNT_OFF + 16)

__global__ __launch_bounds__(1024, 1) void k_persist(float* __restrict__ out)
{
    extern __shared__ char sm[];
    int8_t*         w2sh  = (int8_t*)sm;
    unsigned short* list0 = (unsigned short*)(sm + SM_LIST_OFF);
    unsigned short* list1 = list0 + N_HID;
    int*            cnt   = (int*)(sm + SM_CNT_OFF);

    const int tid = threadIdx.x;

    // copy w2 (already int8) into SMEM with 4B transfers
    for (int i = tid; i < (N_OUT * N_HID) / 4; i += 1024)
        ((int*)w2sh)[i] = ((const int*)g_w2s)[i];
    if (tid == 0) { cnt[0] = 0; cnt[1] = 0; cnt[2] = 0; }
    __syncthreads();

    int mem0 = 0, mem1 = 0, mem2 = 0, mem3 = 0;
    int syn0 = 0, syn1 = 0, syn2 = 0, syn3 = 0;
    unsigned prev = 0;
    int rmem = 0, rsyn = 0;

    const int hbase = tid * 4;

    int ir = 2, iw = 0, iz = 1;     // counter rotation: read, write, zero

    for (int t = 0; t < T_STEPS; ++t) {
        unsigned short* wr = (t & 1) ? list1 : list0;   // written this step
        unsigned short* rd = (t & 1) ? list0 : list1;   // written at t-1

        // feed-forward currents for this step (L2; overlaps gather)
        const int4 inv = *(const int4*)(g_in + (size_t)t * N_HID + hbase);

        // sparse recurrent feedback from spikes(t-1); 8-deep load batching
        int n = cnt[ir];
        int fb0 = 0, fb1 = 0, fb2 = 0, fb3 = 0;
        int idx = 0;
        for (; idx + 8 <= n; idx += 8) {
            int w[8];
            #pragma unroll
            for (int j = 0; j < 8; ++j)
                w[j] = *(const int*)(g_v1T + (size_t)rd[idx + j] * N_HID + hbase);
            #pragma unroll
            for (int j = 0; j < 8; ++j) {
                fb0 += (w[j] << 24) >> 24;
                fb1 += (w[j] << 16) >> 24;
                fb2 += (w[j] <<  8) >> 24;
                fb3 +=  w[j] >> 24;
            }
        }
        for (; idx < n; ++idx) {
            int w = *(const int*)(g_v1T + (size_t)rd[idx] * N_HID + hbase);
            fb0 += (w << 24) >> 24;
            fb1 += (w << 16) >> 24;
            fb2 += (w <<  8) >> 24;
            fb3 +=  w >> 24;
        }

        // hidden LIF: reset -> threshold -> decay/integrate
        unsigned newprev = 0;
        {
            int m, o;
            m = (prev & 1u) ? 0 : mem0;  o = (m > 1);
            mem0 = m - (m >> 3) + syn0;
            syn0 = syn0 - (syn0 >> 4) + inv.x + fb0;
            if (o) { int pos = atomicAdd(&cnt[iw], 1); wr[pos] = (unsigned short)(hbase + 0); newprev |= 1u; }

            m = (prev & 2u) ? 0 : mem1;  o = (m > 1);
            mem1 = m - (m >> 3) + syn1;
            syn1 = syn1 - (syn1 >> 4) + inv.y + fb1;
            if (o) { int pos = atomicAdd(&cnt[iw], 1); wr[pos] = (unsigned short)(hbase + 1); newprev |= 2u; }

            m = (prev & 4u) ? 0 : mem2;  o = (m > 1);
            mem2 = m - (m >> 3) + syn2;
            syn2 = syn2 - (syn2 >> 4) + inv.z + fb2;
            if (o) { int pos = atomicAdd(&cnt[iw], 1); wr[pos] = (unsigned short)(hbase + 2); newprev |= 4u; }

            m = (prev & 8u) ? 0 : mem3;  o = (m > 1);
            mem3 = m - (m >> 3) + syn3;
            syn3 = syn3 - (syn3 >> 4) + inv.w + fb3;
            if (o) { int pos = atomicAdd(&cnt[iw], 1); wr[pos] = (unsigned short)(hbase + 3); newprev |= 8u; }
        }
        prev = newprev;

        if (tid == 0) cnt[iz] = 0;             // recycle for step t+1 (see audit)

        __syncthreads();                        // single barrier per step

        // readout LIF on 20 threads (uses THIS step's new spikes)
        if (tid < N_OUT) {
            int n2 = cnt[iw];
            const int8_t* w2row = w2sh + tid * N_HID;
            int ro = 0;
            for (int i = 0; i < n2; ++i) ro += w2row[wr[i]];
            rmem = rmem - (rmem >> 3) + rsyn;        // old rsyn
            rsyn = rsyn - (rsyn >> 4) + ro;
            // output buffer is float32; |rmem| < 2^24 so conversion exact
            out[(size_t)tid * T_STEPS + t] = (float)rmem;
        }

        // rotate counter roles
        int t0 = ir; ir = iw; iw = iz; iz = t0;
    }
}

// ---------------------------------------------------------------------------
// Launch
// ---------------------------------------------------------------------------
extern "C" void kernel_launch(void* const* d_in, const int* in_sizes, int n_in,
                              void* d_out, int out_size) {
    // Robust input identification: all element counts are distinct.
    const void* spk = d_in[0];
    const void* w1  = d_in[1];
    const void* v1  = d_in[2];
    const void* w2  = d_in[3];
    for (int i = 0; i < n_in && i < 4; ++i) {
        int s = in_sizes[i];
        if      (s == T_STEPS * N_IN)  spk = d_in[i];
        else if (s == N_HID * N_IN)    w1  = d_in[i];
        else if (s == N_HID * N_HID)   v1  = d_in[i];
        else if (s == N_OUT * N_HID)   w2  = d_in[i];
    }

    k_detect<<<1, 1>>>(w2);

    k_pack_spk<<<(T_PAD * K_PAD + 255) / 256, 256>>>(spk);
    k_pack_w1 <<<(N_HID * K_PAD + 255) / 256, 256>>>(w1);
    k_pack_w2 <<<(N_OUT * N_HID + 255) / 256, 256>>>(w2);
    k_v1_transpose<<<dim3(N_HID / 32, N_HID / 32), dim3(32, 32)>>>(v1);

    k_gemm_in<<<(T_PAD / 16) * (N_HID / 64) / 8, 256>>>();

    cudaFuncSetAttribute(k_persist, cudaFuncAttributeMaxDynamicSharedMemorySize,
                         SM_TOTAL);
    k_persist<<<1, 1024, SM_TOTAL>>>((float*)d_out);
}